// round 1
// baseline (speedup 1.0000x reference)
#include <cuda_runtime.h>

// NCC: image (8,3,1024,1024) f32, template (3,31,31) f32, stride 1, pad 15.
// out (8,1024,1024) f32 = mean_c[ conv(img, norm_t) / (sqrt(m2-m1^2)+eps) ], NaN->0
//
// Strategy:
//  - prep kernel normalizes the template per channel into two padded copies:
//      g_tA[c][i][j] = nt[i][j]   (j<31, col 31 = 0)
//      g_tB[c][i][j] = nt[i][j+1] (j<30, cols 30,31 = 0)    <- shifted copy so that
//    ALL packed-pair operands (image and template) are aligned float4 halves.
//  - main kernel: 32x32 output tile per block, 64 threads, each thread 4x4 pixels.
//    Halo (62x64, zero padded) in smem; box sums via separable sliding windows;
//    template correlation via fma.rn.f32x2 packed over the tap dimension.

#define EPSF 1e-9f
#define INV961 (1.0f/961.0f)

__device__ float g_tA[3][31][32];
__device__ float g_tB[3][31][32];

__device__ __forceinline__ void dfma(float2 &d, const float2 a, const float2 b) {
    asm("fma.rn.f32x2 %0, %1, %2, %0;"
        : "+l"(reinterpret_cast<unsigned long long &>(d))
        : "l"(reinterpret_cast<const unsigned long long &>(a)),
          "l"(reinterpret_cast<const unsigned long long &>(b)));
}

__global__ void ncc_prep(const float* __restrict__ t) {
    const int c = blockIdx.x;
    const int lane = threadIdx.x;
    const float* tc = t + c * 961;
    float s = 0.f;
    for (int i = lane; i < 961; i += 32) s += tc[i];
#pragma unroll
    for (int o = 16; o > 0; o >>= 1) s += __shfl_xor_sync(0xffffffffu, s, o);
    const float mu = s * INV961;
    float v = 0.f;
    for (int i = lane; i < 961; i += 32) { float d = tc[i] - mu; v = fmaf(d, d, v); }
#pragma unroll
    for (int o = 16; o > 0; o >>= 1) v += __shfl_xor_sync(0xffffffffu, v, o);
    const float sd = sqrtf(v * INV961);
    const float scale = 1.f / ((sd + EPSF) * 961.f);
    for (int idx = lane; idx < 31 * 32; idx += 32) {
        const int ri = idx >> 5, j = idx & 31;
        g_tA[c][ri][j] = (j < 31) ? (tc[ri * 31 + j] - mu) * scale : 0.f;
        g_tB[c][ri][j] = (j < 30) ? (tc[ri * 31 + j + 1] - mu) * scale : 0.f;
    }
}

__global__ __launch_bounds__(64)
void ncc_main(const float* __restrict__ img, float* __restrict__ out) {
    __shared__ __align__(16) float sh_halo[62][64];   // zero-padded halo, cols 62,63 = 0
    __shared__ __align__(16) float sh_h1[62][32];     // horizontal box sums
    __shared__ __align__(16) float sh_h2[62][32];     // horizontal box sums of squares
    __shared__ __align__(16) float sh_tA[31 * 32];
    __shared__ __align__(16) float sh_tB[31 * 32];

    const int tx = threadIdx.x, ty = threadIdx.y;
    const int tid = ty * 8 + tx;
    const int bx = blockIdx.x, by = blockIdx.y, n = blockIdx.z;
    const int x0 = tx * 4, y0 = ty * 4;          // within-tile pixel origin (4x4 per thread)
    const int gx0 = bx * 32, gy0 = by * 32;

    float oacc[4][4];
#pragma unroll
    for (int p = 0; p < 4; ++p)
#pragma unroll
        for (int k = 0; k < 4; ++k) oacc[p][k] = 0.f;

    for (int c = 0; c < 3; ++c) {
        __syncthreads();   // previous channel's readers done; safe to overwrite smem

        // ---- load normalized template (both copies) ----
        {
            const float* gA = &g_tA[c][0][0];
            const float* gB = &g_tB[c][0][0];
            for (int i = tid; i < 31 * 32; i += 64) { sh_tA[i] = gA[i]; sh_tB[i] = gB[i]; }
        }
        // ---- load halo (62 rows x 62 cols real, cols 62..63 zero) ----
        {
            const float* plane = img + ((size_t)(n * 3 + c) << 20);
            const int col = tid;
            const int gx = gx0 - 15 + col;
            const bool xok = (col < 62) && ((unsigned)gx < 1024u);
#pragma unroll 1
            for (int r = 0; r < 62; ++r) {
                const int gy = gy0 - 15 + r;
                float v = 0.f;
                if (xok && ((unsigned)gy < 1024u)) v = plane[(gy << 10) + gx];
                sh_halo[r][col] = v;
            }
        }
        __syncthreads();

        // ---- horizontal box sums: 62 rows x 8 groups of 4 columns ----
#pragma unroll 1
        for (int t = tid; t < 62 * 8; t += 64) {
            const int r = t >> 3, xg = (t & 7) << 2;
            const float* row = &sh_halo[r][xg];
            float f[36];
#pragma unroll
            for (int q = 0; q < 9; ++q) {
                const float4 v = *(const float4*)(row + 4 * q);
                f[4*q] = v.x; f[4*q+1] = v.y; f[4*q+2] = v.z; f[4*q+3] = v.w;
            }
            float s = 0.f, qq = 0.f;
#pragma unroll
            for (int j = 0; j < 31; ++j) { s += f[j]; qq = fmaf(f[j], f[j], qq); }
            const float s0 = s;
            const float s1 = s0 - f[0] + f[31];
            const float s2 = s1 - f[1] + f[32];
            const float s3 = s2 - f[2] + f[33];
            const float q0 = qq;
            const float q1 = q0 - f[0]*f[0] + f[31]*f[31];
            const float q2 = q1 - f[1]*f[1] + f[32]*f[32];
            const float q3 = q2 - f[2]*f[2] + f[33]*f[33];
            *(float4*)&sh_h1[r][xg] = make_float4(s0, s1, s2, s3);
            *(float4*)&sh_h2[r][xg] = make_float4(q0, q1, q2, q3);
        }

        // ---- template correlation: packed f32x2 over tap dimension ----
        float2 acc[4][4];
#pragma unroll
        for (int p = 0; p < 4; ++p)
#pragma unroll
            for (int k = 0; k < 4; ++k) acc[p][k] = make_float2(0.f, 0.f);

#pragma unroll 1
        for (int r = 0; r < 34; ++r) {
            const float* hrow = &sh_halo[y0 + r][x0];
            float4 Wv[9];
#pragma unroll
            for (int q = 0; q < 9; ++q) Wv[q] = *(const float4*)(hrow + 4 * q);
#pragma unroll
            for (int p = 0; p < 4; ++p) {
                const int i = r - p;                 // template row (uniform branch)
                if ((unsigned)i > 30u) continue;
                const float4* TA = (const float4*)(sh_tA + (i << 5));
                const float4* TB = (const float4*)(sh_tB + (i << 5));
                float2 a0 = acc[p][0], a1 = acc[p][1], a2 = acc[p][2], a3 = acc[p][3];
                const float t0 = sh_tA[i << 5];
#pragma unroll
                for (int q = 0; q < 8; ++q) {
                    const float4 ta = TA[q], tb = TB[q];
                    const float4 w = Wv[q], wn = Wv[q + 1];
                    const float2 wlo = make_float2(w.x,  w.y),  whi = make_float2(w.z,  w.w);
                    const float2 nlo = make_float2(wn.x, wn.y), nhi = make_float2(wn.z, wn.w);
                    const float2 alo = make_float2(ta.x, ta.y), ahi = make_float2(ta.z, ta.w);
                    const float2 blo = make_float2(tb.x, tb.y), bhi = make_float2(tb.z, tb.w);
                    dfma(a0, wlo, alo); dfma(a0, whi, ahi);   // pixel x0+0
                    dfma(a2, whi, alo); dfma(a2, nlo, ahi);   // pixel x0+2
                    dfma(a1, whi, blo); dfma(a1, nlo, bhi);   // pixel x0+1 (shifted tmpl)
                    dfma(a3, nlo, blo); dfma(a3, nhi, bhi);   // pixel x0+3 (shifted tmpl)
                }
                a1.x = fmaf(Wv[0].y, t0, a1.x);               // tap 0 scalars for odd pixels
                a3.x = fmaf(Wv[0].w, t0, a3.x);
                acc[p][0] = a0; acc[p][1] = a1; acc[p][2] = a2; acc[p][3] = a3;
            }
        }
        __syncthreads();   // hsum ready; also everyone done with halo

        // ---- vertical box sums (sliding over p) + combine ----
        float s1v[4] = {0.f, 0.f, 0.f, 0.f};
        float s2v[4] = {0.f, 0.f, 0.f, 0.f};
#pragma unroll 1
        for (int i = 0; i < 31; ++i) {
            const float4 h1 = *(const float4*)&sh_h1[y0 + i][x0];
            const float4 h2 = *(const float4*)&sh_h2[y0 + i][x0];
            s1v[0] += h1.x; s1v[1] += h1.y; s1v[2] += h1.z; s1v[3] += h1.w;
            s2v[0] += h2.x; s2v[1] += h2.y; s2v[2] += h2.z; s2v[3] += h2.w;
        }
#pragma unroll
        for (int p = 0; p < 4; ++p) {
            if (p > 0) {
                const float4 o1 = *(const float4*)&sh_h1[y0 + p - 1][x0];
                const float4 n1 = *(const float4*)&sh_h1[y0 + p + 30][x0];
                const float4 o2 = *(const float4*)&sh_h2[y0 + p - 1][x0];
                const float4 n2 = *(const float4*)&sh_h2[y0 + p + 30][x0];
                s1v[0] += n1.x - o1.x; s1v[1] += n1.y - o1.y;
                s1v[2] += n1.z - o1.z; s1v[3] += n1.w - o1.w;
                s2v[0] += n2.x - o2.x; s2v[1] += n2.y - o2.y;
                s2v[2] += n2.z - o2.z; s2v[3] += n2.w - o2.w;
            }
#pragma unroll
            for (int k = 0; k < 4; ++k) {
                const float st  = acc[p][k].x + acc[p][k].y;
                const float m   = s1v[k] * INV961;
                const float var = fmaf(-m, m, s2v[k] * INV961);
                const float sd  = sqrtf(var);                 // var<0 -> NaN (matches ref)
                oacc[p][k] += st / (sd + EPSF);
            }
        }
    }

    // ---- write out: mean over channels, NaN -> 0 ----
#pragma unroll
    for (int p = 0; p < 4; ++p) {
        float4 v;
        float r0 = oacc[p][0] * (1.0f/3.0f); v.x = (r0 == r0) ? r0 : 0.f;
        float r1 = oacc[p][1] * (1.0f/3.0f); v.y = (r1 == r1) ? r1 : 0.f;
        float r2 = oacc[p][2] * (1.0f/3.0f); v.z = (r2 == r2) ? r2 : 0.f;
        float r3 = oacc[p][3] * (1.0f/3.0f); v.w = (r3 == r3) ? r3 : 0.f;
        float* dst = out + (((size_t)n << 20) + ((size_t)(gy0 + y0 + p) << 10) + gx0 + x0);
        *(float4*)dst = v;
    }
}

extern "C" void kernel_launch(void* const* d_in, const int* in_sizes, int n_in,
                              void* d_out, int out_size) {
    (void)in_sizes; (void)n_in; (void)out_size;
    const float* img  = (const float*)d_in[0];
    const float* tmpl = (const float*)d_in[1];
    float* out = (float*)d_out;

    ncc_prep<<<3, 32>>>(tmpl);
    dim3 grid(32, 32, 8);
    dim3 block(8, 8);
    ncc_main<<<grid, block>>>(img, out);
}